// round 9
// baseline (speedup 1.0000x reference)
#include <cuda_runtime.h>
#include <string.h>
#include <stdint.h>

#define EPS 1e-5f

// ---------------- folded-weight scratch (device globals: allowed) ----------
__device__ __align__(16) float g_W1t[512 * 192];     // [c][j], BN1 scale folded
__device__ __align__(16) float g_b1f[192];           // BN1 folded bias
__device__ __align__(16) float g_W4t[64 * 512];      // [d][c], BN2 scale folded
__device__ __align__(16) float g_c4f[512];           // BN2 folded bias

// ---------------- prep: fold BN into weights -------------------------------
__global__ void prep_kernel(const float* __restrict__ W123, const float* __restrict__ b123,
                            const float* __restrict__ g123, const float* __restrict__ be123,
                            const float* __restrict__ m123, const float* __restrict__ v123,
                            const float* __restrict__ W4,   const float* __restrict__ b4,
                            const float* __restrict__ g4,   const float* __restrict__ be4,
                            const float* __restrict__ m4,   const float* __restrict__ v4)
{
    int idx = blockIdx.x * blockDim.x + threadIdx.x;
    if (idx < 512 * 192) {
        int c = idx / 192, j = idx % 192;
        float s = g123[j] * rsqrtf(v123[j] + EPS);
        g_W1t[c * 192 + j] = W123[j * 512 + c] * s;
    }
    int i2 = idx - 512 * 192;
    if (i2 >= 0 && i2 < 192) {
        float s = g123[i2] * rsqrtf(v123[i2] + EPS);
        g_b1f[i2] = (b123[i2] - m123[i2]) * s + be123[i2];
    }
    int i3 = idx - (512 * 192 + 192);
    if (i3 >= 0 && i3 < 64 * 512) {
        int d = i3 / 512, c = i3 % 512;
        float s = g4[c] * rsqrtf(v4[c] + EPS);
        g_W4t[i3] = W4[c * 64 + d] * s;
    }
    int i4 = idx - (512 * 192 + 192 + 64 * 512);
    if (i4 >= 0 && i4 < 512) {
        float s = g4[i4] * rsqrtf(v4[i4] + EPS);
        g_c4f[i4] = (b4[i4] - m4[i4]) * s + be4[i4];
    }
}

// ---------------- helpers ---------------------------------------------------
__device__ __forceinline__ float2 ffma2(float2 a, float2 b, float2 c) {
    unsigned long long au, bu, cu, du;
    memcpy(&au, &a, 8); memcpy(&bu, &b, 8); memcpy(&cu, &c, 8);
    asm("fma.rn.f32x2 %0, %1, %2, %3;" : "=l"(du) : "l"(au), "l"(bu), "l"(cu));
    float2 d; memcpy(&d, &du, 8); return d;
}
__device__ __forceinline__ uint32_t smem_u32(const void* p) {
    uint32_t a;
    asm("{ .reg .u64 t; cvta.to.shared.u64 t, %1; cvt.u32.u64 %0, t; }" : "=r"(a) : "l"(p));
    return a;
}
__device__ __forceinline__ void mbar_init(uint32_t a, uint32_t cnt) {
    asm volatile("mbarrier.init.shared.b64 [%0], %1;" :: "r"(a), "r"(cnt) : "memory");
}
__device__ __forceinline__ void mbar_expect_tx(uint32_t a, uint32_t bytes) {
    asm volatile("mbarrier.arrive.expect_tx.shared.b64 _, [%0], %1;" :: "r"(a), "r"(bytes) : "memory");
}
__device__ __forceinline__ void mbar_wait(uint32_t a, uint32_t parity) {
    asm volatile(
        "{\n\t.reg .pred P;\n\t"
        "WL%=:\n\t"
        "mbarrier.try_wait.parity.acquire.cta.shared::cta.b64 P, [%0], %1, 0x989680;\n\t"
        "@P bra WD%=;\n\t"
        "bra.uni WL%=;\n\t"
        "WD%=:\n\t}"
        :: "r"(a), "r"(parity) : "memory");
}
__device__ __forceinline__ void bulk_g2s(uint32_t dst_smem, const float* gsrc,
                                         uint32_t bytes, uint32_t mbar) {
    asm volatile(
        "cp.async.bulk.shared::cluster.global.mbarrier::complete_tx::bytes [%0], [%1], %2, [%3];"
        :: "r"(dst_smem), "l"(gsrc), "r"(bytes), "r"(mbar) : "memory");
}
#define FENCE_ASYNC() asm volatile("fence.proxy.async.shared::cta;" ::: "memory")

// SMEM (floats):
//   [0, 34816)        A_T[512][68]; reused after GEMM1: W4s[64][512]
//   [34816, 51328)    GEMM1 weight tiles 2x6144 / act[64][192] / yS 2 x (16x516)
//   [51328, 55488)    sATT 16 x 260
//   [55488, ...)      3 mbarriers
#define SMF 55496

__global__ void __launch_bounds__(768, 1)
fused_kernel(const float* __restrict__ x, float* __restrict__ out)
{
    extern __shared__ float sm[];
    float* sAT  = sm;                  // later: W4s
    float* sB   = sm + 34816;          // later: act, then yS buffers
    float* sATT = sm + 51328;
    const uint32_t smb  = smem_u32(sm);
    const uint32_t smbB = smb + 34816u * 4u;
    const uint32_t MBAR = smb + 55488u * 4u;

    const int t    = threadIdx.x;
    const int warp = t >> 5;           // 24 warps
    const int lane = t & 31;
    const int rh   = warp & 1;
    const int cg1  = warp >> 1;        // GEMM1 col-group 0..11
    const int n0   = blockIdx.x * 16;

    if (t == 0) {
        mbar_init(MBAR + 0,  1);
        mbar_init(MBAR + 8,  1);
        mbar_init(MBAR + 16, 1);
    }
    __syncthreads();
    if (t == 0) {
        mbar_expect_tx(MBAR + 0, 24576);
        bulk_g2s(smbB,          g_W1t,        24576, MBAR + 0);
        mbar_expect_tx(MBAR + 8, 24576);
        bulk_g2s(smbB + 24576u, g_W1t + 6144, 24576, MBAR + 8);
    }

    const float4* xb = (const float4*)x;

    // ---- Phase 0: gather xs chunks 0,1 only (rest pipelined into GEMM1).
    //      warp w (<16) = sample w; lane = channel within chunk.
    if (warp < 16) {
        #pragma unroll
        for (int ch = 0; ch < 2; ch++) {
            int c = ch * 32 + lane;
            long base = ((long)((n0 + warp) * 512 + c)) * 4;
            float4 v0 = __ldg(&xb[base + 0]);               // h=0: w 0..3
            float4 v1 = __ldg(&xb[base + 2]);               // h=2: w 0..3
            *(float4*)&sAT[c * 68 + 4 * warp] = make_float4(v0.x, v0.z, v1.x, v1.z);
        }
    }
    __syncthreads();

    // ---- Phase 1: GEMM1 [64r][192c]; warp 32r x 16c; LDS.128 conflict-free;
    //      A_T chunk st+2 gathered (LDG before fma block, STS after) in stage st.
    float2 acc[4][2];
    #pragma unroll
    for (int r = 0; r < 4; r++) {
        acc[r][0] = make_float2(0.f, 0.f);
        acc[r][1] = make_float2(0.f, 0.f);
    }
    const int r0 = rh * 32 + (lane >> 2) * 4;
    const int j0 = cg1 * 16 + (lane & 3) * 4;

    for (int st = 0; st < 16; st++) {
        mbar_wait(MBAR + 8u * (st & 1), (st >> 1) & 1);

        const bool doPref = (st + 2 < 16) && (warp < 16);
        float4 pv0, pv1;
        int pc = (st + 2) * 32 + lane;
        if (doPref) {
            long base = ((long)((n0 + warp) * 512 + pc)) * 4;
            pv0 = __ldg(&xb[base + 0]);
            pv1 = __ldg(&xb[base + 2]);
        }

        const float* bbase = sB + (st & 1) * 6144 + j0;
        const float* abase = sAT + (st * 32) * 68 + r0;
        #pragma unroll 8
        for (int kk = 0; kk < 32; kk++) {
            float4 a = *(const float4*)&abase[kk * 68];
            float4 b = *(const float4*)&bbase[kk * 192];
            float2 b01 = make_float2(b.x, b.y), b23 = make_float2(b.z, b.w);
            acc[0][0] = ffma2(make_float2(a.x, a.x), b01, acc[0][0]);
            acc[0][1] = ffma2(make_float2(a.x, a.x), b23, acc[0][1]);
            acc[1][0] = ffma2(make_float2(a.y, a.y), b01, acc[1][0]);
            acc[1][1] = ffma2(make_float2(a.y, a.y), b23, acc[1][1]);
            acc[2][0] = ffma2(make_float2(a.z, a.z), b01, acc[2][0]);
            acc[2][1] = ffma2(make_float2(a.z, a.z), b23, acc[2][1]);
            acc[3][0] = ffma2(make_float2(a.w, a.w), b01, acc[3][0]);
            acc[3][1] = ffma2(make_float2(a.w, a.w), b23, acc[3][1]);
        }

        if (doPref)
            *(float4*)&sAT[pc * 68 + 4 * warp] = make_float4(pv0.x, pv0.z, pv1.x, pv1.z);

        __syncthreads();   // weight buffer consumed + A_T chunk st+2 visible

        if (st + 2 < 16 && t == 0) {
            mbar_expect_tx(MBAR + 8u * (st & 1), 24576);
            bulk_g2s(smbB + 24576u * (st & 1), g_W1t + (st + 2) * 6144, 24576,
                     MBAR + 8u * (st & 1));
        }
    }
    // sAT & sB dead. Kick off full W4 load into old sAT region.
    if (t == 0) {
        FENCE_ASYNC();
        mbar_expect_tx(MBAR + 16, 131072);
        bulk_g2s(smb, g_W4t, 131072, MBAR + 16);
    }

    // ---- act = relu(acc + bias) -> act[64][192] in old sB region
    float* act = sB;
    {
        float4 bias = __ldg((const float4*)&g_b1f[j0]);
        #pragma unroll
        for (int r = 0; r < 4; r++) {
            float4 o;
            o.x = fmaxf(acc[r][0].x + bias.x, 0.f);
            o.y = fmaxf(acc[r][0].y + bias.y, 0.f);
            o.z = fmaxf(acc[r][1].x + bias.z, 0.f);
            o.w = fmaxf(acc[r][1].y + bias.w, 0.f);
            *(float4*)&act[(r0 + r) * 192 + j0] = o;
        }
    }
    __syncthreads();   // act complete

    // ---- Phase 2: warp-local 4x4 attention (warps 0..15, warp = sample)
    if (warp < 16) {
        const int s = warp, g = lane;
        float2 q2[4], k2[4], v2[4];
        #pragma unroll
        for (int l = 0; l < 4; l++) {
            const float* ar = act + (4 * s + l) * 192;
            q2[l] = *(const float2*)&ar[2 * g];
            k2[l] = *(const float2*)&ar[2 * g + 64];
            v2[l] = *(const float2*)&ar[2 * g + 128];
        }
        float sc[16];
        #pragma unroll
        for (int l = 0; l < 4; l++)
            #pragma unroll
            for (int m = 0; m < 4; m++)
                sc[l * 4 + m] = q2[l].x * k2[m].x + q2[l].y * k2[m].y;
        #pragma unroll
        for (int off = 16; off > 0; off >>= 1)
            #pragma unroll
            for (int i = 0; i < 16; i++)
                sc[i] += __shfl_xor_sync(0xffffffffu, sc[i], off);

        #pragma unroll
        for (int l = 0; l < 4; l++) {
            float s0 = sc[l*4+0], s1 = sc[l*4+1], s2 = sc[l*4+2], s3 = sc[l*4+3];
            float mx = fmaxf(fmaxf(s0, s1), fmaxf(s2, s3));
            float e0 = __expf(s0 - mx), e1 = __expf(s1 - mx);
            float e2 = __expf(s2 - mx), e3 = __expf(s3 - mx);
            float inv = 1.f / (e0 + e1 + e2 + e3);
            float ax = (e0*v2[0].x + e1*v2[1].x + e2*v2[2].x + e3*v2[3].x) * inv;
            float ay = (e0*v2[0].y + e1*v2[1].y + e2*v2[2].y + e3*v2[3].y) * inv;
            sATT[s * 260 + (2*g)   * 4 + l] = ax;
            sATT[s * 260 + (2*g+1) * 4 + l] = ay;
        }
    }
    __syncthreads();          // sATT complete; act dead -> yS region
    mbar_wait(MBAR + 16, 0);  // W4s resident

    // ---- Phase 3: GEMM2 (warps 0..15) overlapped with epilogue (warps 16..23)
    const float* W4s = sm;
    const int sI  = lane & 15;
    const int cgr = lane >> 4;

    auto compute_y = [&](int cc) {
        float* yb = sB + (cc & 1) * 8256;
        const int cb = cc * 128 + warp * 8 + cgr * 4;      // 4 consecutive c
        float2 y01[4], y23[4];
        #pragma unroll
        for (int cp = 0; cp < 4; cp++) {
            y01[cp] = make_float2(0.f, 0.f);
            y23[cp] = make_float2(0.f, 0.f);
        }
        const float* attn = sATT + sI * 260;
        const float* wp   = W4s + cb;
        #pragma unroll 4
        for (int d = 0; d < 64; d++) {
            float4 av = *(const float4*)&attn[d * 4];
            float4 wv = *(const float4*)&wp[d * 512];
            float2 a01 = make_float2(av.x, av.y), a23 = make_float2(av.z, av.w);
            const float* wvp = &wv.x;
            #pragma unroll
            for (int cp = 0; cp < 4; cp++) {
                float2 wb = make_float2(wvp[cp], wvp[cp]);
                y01[cp] = ffma2(a01, wb, y01[cp]);
                y23[cp] = ffma2(a23, wb, y23[cp]);
            }
        }
        float4 cf = __ldg((const float4*)&g_c4f[cb]);
        const float* cfp = &cf.x;
        const int fb = (warp * 8 + cgr * 4) * 4;
        #pragma unroll
        for (int cp = 0; cp < 4; cp++) {
            *(float4*)&yb[sI * 516 + fb + cp * 4] =
                make_float4(y01[cp].x + cfp[cp], y01[cp].y + cfp[cp],
                            y23[cp].x + cfp[cp], y23[cp].y + cfp[cp]);
        }
    };
    auto epilogue = [&](int cc, int wfirst, int wcount) {
        const float* ys = sB + (cc & 1) * 8256;
        for (int u = warp - wfirst; u < 256; u += wcount) {
            const int s = u >> 4, i = u & 15;
            const int f = i * 32 + lane;
            float yv = ys[s * 516 + f];
            long b4i = ((long)(n0 + s) * 512 + cc * 128) * 4 + f;
            float4 v = __ldg(&xb[b4i]);
            v.x += yv; v.y += yv; v.z += yv; v.w += yv;
            ((float4*)out)[b4i] = v;
        }
    };

    if (warp < 16) compute_y(0);
    __syncthreads();
    #pragma unroll
    for (int cc = 1; cc < 4; cc++) {
        if (warp < 16) compute_y(cc);
        else           epilogue(cc - 1, 16, 8);
        __syncthreads();
    }
    epilogue(3, 0, 24);
}

extern "C" void kernel_launch(void* const* d_in, const int* in_sizes, int n_in,
                              void* d_out, int out_size)
{
    const float* x    = (const float*)d_in[0];
    const float* W123 = (const float*)d_in[1];
    const float* b123 = (const float*)d_in[2];
    const float* g123 = (const float*)d_in[3];
    const float* be123= (const float*)d_in[4];
    const float* m123 = (const float*)d_in[5];
    const float* v123 = (const float*)d_in[6];
    const float* W4   = (const float*)d_in[7];
    const float* b4   = (const float*)d_in[8];
    const float* g4   = (const float*)d_in[9];
    const float* be4  = (const float*)d_in[10];
    const float* m4   = (const float*)d_in[11];
    const float* v4   = (const float*)d_in[12];

    int N = in_sizes[0] / (512 * 16);   // 2048

    prep_kernel<<<515, 256>>>(W123, b123, g123, be123, m123, v123,
                              W4, b4, g4, be4, m4, v4);

    cudaFuncSetAttribute(fused_kernel, cudaFuncAttributeMaxDynamicSharedMemorySize,
                         SMF * 4);
    fused_kernel<<<N / 16, 768, SMF * 4>>>(x, (float*)d_out);
}

// round 10
// speedup vs baseline: 1.0152x; 1.0152x over previous
#include <cuda_runtime.h>
#include <string.h>
#include <stdint.h>

#define EPS 1e-5f

// ---------------- folded-weight scratch (device globals: allowed) ----------
__device__ __align__(16) float g_W1t[512 * 192];     // [c][j], BN1 scale folded
__device__ __align__(16) float g_b1f[192];           // BN1 folded bias
__device__ __align__(16) float g_W4t[64 * 512];      // [d][c], BN2 scale folded
__device__ __align__(16) float g_c4f[512];           // BN2 folded bias

// ---------------- prep: fold BN into weights -------------------------------
__global__ void prep_kernel(const float* __restrict__ W123, const float* __restrict__ b123,
                            const float* __restrict__ g123, const float* __restrict__ be123,
                            const float* __restrict__ m123, const float* __restrict__ v123,
                            const float* __restrict__ W4,   const float* __restrict__ b4,
                            const float* __restrict__ g4,   const float* __restrict__ be4,
                            const float* __restrict__ m4,   const float* __restrict__ v4)
{
    int idx = blockIdx.x * blockDim.x + threadIdx.x;
    if (idx < 512 * 192) {
        int c = idx / 192, j = idx % 192;
        float s = g123[j] * rsqrtf(v123[j] + EPS);
        g_W1t[c * 192 + j] = W123[j * 512 + c] * s;
    }
    int i2 = idx - 512 * 192;
    if (i2 >= 0 && i2 < 192) {
        float s = g123[i2] * rsqrtf(v123[i2] + EPS);
        g_b1f[i2] = (b123[i2] - m123[i2]) * s + be123[i2];
    }
    int i3 = idx - (512 * 192 + 192);
    if (i3 >= 0 && i3 < 64 * 512) {
        int d = i3 / 512, c = i3 % 512;
        float s = g4[c] * rsqrtf(v4[c] + EPS);
        g_W4t[i3] = W4[c * 64 + d] * s;
    }
    int i4 = idx - (512 * 192 + 192 + 64 * 512);
    if (i4 >= 0 && i4 < 512) {
        float s = g4[i4] * rsqrtf(v4[i4] + EPS);
        g_c4f[i4] = (b4[i4] - m4[i4]) * s + be4[i4];
    }
}

// ---------------- helpers ---------------------------------------------------
__device__ __forceinline__ float2 ffma2(float2 a, float2 b, float2 c) {
    unsigned long long au, bu, cu, du;
    memcpy(&au, &a, 8); memcpy(&bu, &b, 8); memcpy(&cu, &c, 8);
    asm("fma.rn.f32x2 %0, %1, %2, %3;" : "=l"(du) : "l"(au), "l"(bu), "l"(cu));
    float2 d; memcpy(&d, &du, 8); return d;
}
__device__ __forceinline__ uint32_t smem_u32(const void* p) {
    uint32_t a;
    asm("{ .reg .u64 t; cvta.to.shared.u64 t, %1; cvt.u32.u64 %0, t; }" : "=r"(a) : "l"(p));
    return a;
}
__device__ __forceinline__ void mbar_init(uint32_t a, uint32_t cnt) {
    asm volatile("mbarrier.init.shared.b64 [%0], %1;" :: "r"(a), "r"(cnt) : "memory");
}
__device__ __forceinline__ void mbar_expect_tx(uint32_t a, uint32_t bytes) {
    asm volatile("mbarrier.arrive.expect_tx.shared.b64 _, [%0], %1;" :: "r"(a), "r"(bytes) : "memory");
}
__device__ __forceinline__ void mbar_wait(uint32_t a, uint32_t parity) {
    asm volatile(
        "{\n\t.reg .pred P;\n\t"
        "WL%=:\n\t"
        "mbarrier.try_wait.parity.acquire.cta.shared::cta.b64 P, [%0], %1, 0x989680;\n\t"
        "@P bra WD%=;\n\t"
        "bra.uni WL%=;\n\t"
        "WD%=:\n\t}"
        :: "r"(a), "r"(parity) : "memory");
}
__device__ __forceinline__ void bulk_g2s(uint32_t dst_smem, const float* gsrc,
                                         uint32_t bytes, uint32_t mbar) {
    asm volatile(
        "cp.async.bulk.shared::cluster.global.mbarrier::complete_tx::bytes [%0], [%1], %2, [%3];"
        :: "r"(dst_smem), "l"(gsrc), "r"(bytes), "r"(mbar) : "memory");
}
#define FENCE_ASYNC() asm volatile("fence.proxy.async.shared::cta;" ::: "memory")

// SMEM (floats):
//   [0, 34816)        A_T[512][68]; reused after GEMM1: W4s[64][512]
//   [34816, 51328)    GEMM1 weight tiles 2x6144 / act[64][192] / yS 2 x (16x516)
//   [51328, 55488)    sATT 16 x 260
//   [55488, ...)      3 mbarriers
#define SMF 55496

__global__ void __launch_bounds__(768, 1)
fused_kernel(const float* __restrict__ x, float* __restrict__ out)
{
    extern __shared__ float sm[];
    float* sAT  = sm;                  // later: W4s
    float* sB   = sm + 34816;          // later: act, then yS buffers
    float* sATT = sm + 51328;
    const uint32_t smb  = smem_u32(sm);
    const uint32_t smbB = smb + 34816u * 4u;
    const uint32_t MBAR = smb + 55488u * 4u;

    const int t    = threadIdx.x;
    const int warp = t >> 5;           // 24 warps
    const int lane = t & 31;
    const int rh   = warp & 1;
    const int cg1  = warp >> 1;        // GEMM1 col-group 0..11
    const int n0   = blockIdx.x * 16;

    if (t == 0) {
        mbar_init(MBAR + 0,  1);
        mbar_init(MBAR + 8,  1);
        mbar_init(MBAR + 16, 1);
    }
    __syncthreads();
    if (t == 0) {
        mbar_expect_tx(MBAR + 0, 24576);
        bulk_g2s(smbB,          g_W1t,        24576, MBAR + 0);
        mbar_expect_tx(MBAR + 8, 24576);
        bulk_g2s(smbB + 24576u, g_W1t + 6144, 24576, MBAR + 8);
    }

    const float4* xb = (const float4*)x;

    // ---- Phase 0: gather xs (strided 2x2 slice) into A_T[c][row], row=4*i+l
    //      unit = (sample i, 16-channel block cb); lane = (c_local, h-sel)
    //      LDG: 8 lines, all sectors used (8 wf); STS.64: 32 distinct banks (1 wf)
    {
        const int cl = lane >> 1;            // c within block, 0..15
        const int hs = lane & 1;             // h selector: 0 -> h=0, 1 -> h=2
        for (int u = warp; u < 512; u += 24) {
            int i  = u >> 5, cb = u & 31;
            int c  = cb * 16 + cl;
            long f4 = ((long)(n0 + i) * 512 + c) * 4 + hs * 2;
            float4 v = __ldg(&xb[f4]);       // row h: w = 0..3
            // l = 2*hs + {0,1} <- (w=0, w=2)
            *(float2*)&sAT[c * 68 + 4 * i + 2 * hs] = make_float2(v.x, v.z);
        }
    }
    __syncthreads();

    // ---- Phase 1: GEMM1 [64r][192c]; warp 32r x 16c; LDS.128 conflict-free
    float2 acc[4][2];
    #pragma unroll
    for (int r = 0; r < 4; r++) {
        acc[r][0] = make_float2(0.f, 0.f);
        acc[r][1] = make_float2(0.f, 0.f);
    }
    const int r0 = rh * 32 + (lane >> 2) * 4;
    const int j0 = cg1 * 16 + (lane & 3) * 4;

    for (int st = 0; st < 16; st++) {
        mbar_wait(MBAR + 8u * (st & 1), (st >> 1) & 1);

        const float* bbase = sB + (st & 1) * 6144 + j0;
        const float* abase = sAT + (st * 32) * 68 + r0;
        #pragma unroll 8
        for (int kk = 0; kk < 32; kk++) {
            float4 a = *(const float4*)&abase[kk * 68];
            float4 b = *(const float4*)&bbase[kk * 192];
            float2 b01 = make_float2(b.x, b.y), b23 = make_float2(b.z, b.w);
            acc[0][0] = ffma2(make_float2(a.x, a.x), b01, acc[0][0]);
            acc[0][1] = ffma2(make_float2(a.x, a.x), b23, acc[0][1]);
            acc[1][0] = ffma2(make_float2(a.y, a.y), b01, acc[1][0]);
            acc[1][1] = ffma2(make_float2(a.y, a.y), b23, acc[1][1]);
            acc[2][0] = ffma2(make_float2(a.z, a.z), b01, acc[2][0]);
            acc[2][1] = ffma2(make_float2(a.z, a.z), b23, acc[2][1]);
            acc[3][0] = ffma2(make_float2(a.w, a.w), b01, acc[3][0]);
            acc[3][1] = ffma2(make_float2(a.w, a.w), b23, acc[3][1]);
        }
        __syncthreads();

        if (st + 2 < 16 && t == 0) {
            mbar_expect_tx(MBAR + 8u * (st & 1), 24576);
            bulk_g2s(smbB + 24576u * (st & 1), g_W1t + (st + 2) * 6144, 24576,
                     MBAR + 8u * (st & 1));
        }
    }
    // sAT & sB dead. Kick off full W4 load into old sAT region.
    if (t == 0) {
        FENCE_ASYNC();
        mbar_expect_tx(MBAR + 16, 131072);
        bulk_g2s(smb, g_W4t, 131072, MBAR + 16);
    }

    // ---- act = relu(acc + bias) -> act[64][192] in old sB region
    float* act = sB;
    {
        float4 bias = __ldg((const float4*)&g_b1f[j0]);
        #pragma unroll
        for (int r = 0; r < 4; r++) {
            float4 o;
            o.x = fmaxf(acc[r][0].x + bias.x, 0.f);
            o.y = fmaxf(acc[r][0].y + bias.y, 0.f);
            o.z = fmaxf(acc[r][1].x + bias.z, 0.f);
            o.w = fmaxf(acc[r][1].y + bias.w, 0.f);
            *(float4*)&act[(r0 + r) * 192 + j0] = o;
        }
    }
    __syncthreads();   // act complete

    // ---- Phase 2: warp-local 4x4 attention (warps 0..15, warp = sample)
    if (warp < 16) {
        const int s = warp, g = lane;
        float2 q2[4], k2[4], v2[4];
        #pragma unroll
        for (int l = 0; l < 4; l++) {
            const float* ar = act + (4 * s + l) * 192;
            q2[l] = *(const float2*)&ar[2 * g];
            k2[l] = *(const float2*)&ar[2 * g + 64];
            v2[l] = *(const float2*)&ar[2 * g + 128];
        }
        float sc[16];
        #pragma unroll
        for (int l = 0; l < 4; l++)
            #pragma unroll
            for (int m = 0; m < 4; m++)
                sc[l * 4 + m] = q2[l].x * k2[m].x + q2[l].y * k2[m].y;
        #pragma unroll
        for (int off = 16; off > 0; off >>= 1)
            #pragma unroll
            for (int i = 0; i < 16; i++)
                sc[i] += __shfl_xor_sync(0xffffffffu, sc[i], off);

        #pragma unroll
        for (int l = 0; l < 4; l++) {
            float s0 = sc[l*4+0], s1 = sc[l*4+1], s2 = sc[l*4+2], s3 = sc[l*4+3];
            float mx = fmaxf(fmaxf(s0, s1), fmaxf(s2, s3));
            float e0 = __expf(s0 - mx), e1 = __expf(s1 - mx);
            float e2 = __expf(s2 - mx), e3 = __expf(s3 - mx);
            float inv = 1.f / (e0 + e1 + e2 + e3);
            float ax = (e0*v2[0].x + e1*v2[1].x + e2*v2[2].x + e3*v2[3].x) * inv;
            float ay = (e0*v2[0].y + e1*v2[1].y + e2*v2[2].y + e3*v2[3].y) * inv;
            sATT[s * 260 + (2*g)   * 4 + l] = ax;
            sATT[s * 260 + (2*g+1) * 4 + l] = ay;
        }
    }
    __syncthreads();          // sATT complete; act dead -> yS region
    mbar_wait(MBAR + 16, 0);  // W4s resident

    // ---- Phase 3: GEMM2 with compute/epilogue warp specialization.
    //      compute is issue-bound -> few warps; epilogue is latency-bound -> many.
    const float* W4s = sm;
    const int sI  = lane & 15;
    const int cgr = lane >> 4;

    // one 8-channel tile of chunk cc, virtual warp vw in 0..15
    auto compute_tile = [&](int cc, int vw) {
        float* yb = sB + (cc & 1) * 8256;
        const int cb = cc * 128 + vw * 8 + cgr * 4;
        float2 y01[4], y23[4];
        #pragma unroll
        for (int cp = 0; cp < 4; cp++) {
            y01[cp] = make_float2(0.f, 0.f);
            y23[cp] = make_float2(0.f, 0.f);
        }
        const float* attn = sATT + sI * 260;
        const float* wp   = W4s + cb;
        #pragma unroll 4
        for (int d = 0; d < 64; d++) {
            float4 av = *(const float4*)&attn[d * 4];
            float4 wv = *(const float4*)&wp[d * 512];
            float2 a01 = make_float2(av.x, av.y), a23 = make_float2(av.z, av.w);
            const float* wvp = &wv.x;
            #pragma unroll
            for (int cp = 0; cp < 4; cp++) {
                float2 wb = make_float2(wvp[cp], wvp[cp]);
                y01[cp] = ffma2(a01, wb, y01[cp]);
                y23[cp] = ffma2(a23, wb, y23[cp]);
            }
        }
        float4 cf = __ldg((const float4*)&g_c4f[cb]);
        const float* cfp = &cf.x;
        const int fb = (vw * 8 + cgr * 4) * 4;
        #pragma unroll
        for (int cp = 0; cp < 4; cp++) {
            *(float4*)&yb[sI * 516 + fb + cp * 4] =
                make_float4(y01[cp].x + cfp[cp], y01[cp].y + cfp[cp],
                            y23[cp].x + cfp[cp], y23[cp].y + cfp[cp]);
        }
    };
    auto epilogue = [&](int cc, int wfirst, int wcount) {
        const float* ys = sB + (cc & 1) * 8256;
        for (int u = warp - wfirst; u < 256; u += wcount) {
            const int s = u >> 4, i = u & 15;
            const int f = i * 32 + lane;
            float yv = ys[s * 516 + f];
            long b4i = ((long)(n0 + s) * 512 + cc * 128) * 4 + f;
            float4 v = __ldg(&xb[b4i]);
            v.x += yv; v.y += yv; v.z += yv; v.w += yv;
            ((float4*)out)[b4i] = v;
        }
    };

    // chunk 0: 16-warp compute (nothing to overlap yet)
    if (warp < 16) compute_tile(0, warp);
    __syncthreads();
    // chunks 1..3: 8-warp compute (2 tiles each) || 16-warp epilogue of cc-1
    #pragma unroll
    for (int cc = 1; cc < 4; cc++) {
        if (warp < 8) {
            compute_tile(cc, warp * 2);
            compute_tile(cc, warp * 2 + 1);
        } else {
            epilogue(cc - 1, 8, 16);
        }
        __syncthreads();
    }
    epilogue(3, 0, 24);
}

extern "C" void kernel_launch(void* const* d_in, const int* in_sizes, int n_in,
                              void* d_out, int out_size)
{
    const float* x    = (const float*)d_in[0];
    const float* W123 = (const float*)d_in[1];
    const float* b123 = (const float*)d_in[2];
    const float* g123 = (const float*)d_in[3];
    const float* be123= (const float*)d_in[4];
    const float* m123 = (const float*)d_in[5];
    const float* v123 = (const float*)d_in[6];
    const float* W4   = (const float*)d_in[7];
    const float* b4   = (const float*)d_in[8];
    const float* g4   = (const float*)d_in[9];
    const float* be4  = (const float*)d_in[10];
    const float* m4   = (const float*)d_in[11];
    const float* v4   = (const float*)d_in[12];

    int N = in_sizes[0] / (512 * 16);   // 2048

    prep_kernel<<<515, 256>>>(W123, b123, g123, be123, m123, v123,
                              W4, b4, g4, be4, m4, v4);

    cudaFuncSetAttribute(fused_kernel, cudaFuncAttributeMaxDynamicSharedMemorySize,
                         SMF * 4);
    fused_kernel<<<N / 16, 768, SMF * 4>>>(x, (float*)d_out);
}

// round 11
// speedup vs baseline: 1.0658x; 1.0499x over previous
#include <cuda_runtime.h>
#include <string.h>
#include <stdint.h>

#define EPS 1e-5f

// ---------------- folded-weight scratch (device globals: allowed) ----------
__device__ __align__(16) float g_W1t[512 * 192];     // [c][j], BN1 scale folded
__device__ __align__(16) float g_b1f[192];           // BN1 folded bias
__device__ __align__(16) float g_W4t[64 * 512];      // [d][c], BN2 scale folded
__device__ __align__(16) float g_c4f[512];           // BN2 folded bias

// ---------------- prep: fold BN into weights -------------------------------
__global__ void prep_kernel(const float* __restrict__ W123, const float* __restrict__ b123,
                            const float* __restrict__ g123, const float* __restrict__ be123,
                            const float* __restrict__ m123, const float* __restrict__ v123,
                            const float* __restrict__ W4,   const float* __restrict__ b4,
                            const float* __restrict__ g4,   const float* __restrict__ be4,
                            const float* __restrict__ m4,   const float* __restrict__ v4)
{
    int idx = blockIdx.x * blockDim.x + threadIdx.x;
    if (idx < 512 * 192) {
        int c = idx / 192, j = idx % 192;
        float s = g123[j] * rsqrtf(v123[j] + EPS);
        g_W1t[c * 192 + j] = W123[j * 512 + c] * s;
    }
    int i2 = idx - 512 * 192;
    if (i2 >= 0 && i2 < 192) {
        float s = g123[i2] * rsqrtf(v123[i2] + EPS);
        g_b1f[i2] = (b123[i2] - m123[i2]) * s + be123[i2];
    }
    int i3 = idx - (512 * 192 + 192);
    if (i3 >= 0 && i3 < 64 * 512) {
        int d = i3 / 512, c = i3 % 512;
        float s = g4[c] * rsqrtf(v4[c] + EPS);
        g_W4t[i3] = W4[c * 64 + d] * s;
    }
    int i4 = idx - (512 * 192 + 192 + 64 * 512);
    if (i4 >= 0 && i4 < 512) {
        float s = g4[i4] * rsqrtf(v4[i4] + EPS);
        g_c4f[i4] = (b4[i4] - m4[i4]) * s + be4[i4];
    }
}

// ---------------- helpers ---------------------------------------------------
__device__ __forceinline__ float2 ffma2(float2 a, float2 b, float2 c) {
    unsigned long long au, bu, cu, du;
    memcpy(&au, &a, 8); memcpy(&bu, &b, 8); memcpy(&cu, &c, 8);
    asm("fma.rn.f32x2 %0, %1, %2, %3;" : "=l"(du) : "l"(au), "l"(bu), "l"(cu));
    float2 d; memcpy(&d, &du, 8); return d;
}
__device__ __forceinline__ uint32_t smem_u32(const void* p) {
    uint32_t a;
    asm("{ .reg .u64 t; cvta.to.shared.u64 t, %1; cvt.u32.u64 %0, t; }" : "=r"(a) : "l"(p));
    return a;
}
__device__ __forceinline__ void mbar_init(uint32_t a, uint32_t cnt) {
    asm volatile("mbarrier.init.shared.b64 [%0], %1;" :: "r"(a), "r"(cnt) : "memory");
}
__device__ __forceinline__ void mbar_expect_tx(uint32_t a, uint32_t bytes) {
    asm volatile("mbarrier.arrive.expect_tx.shared.b64 _, [%0], %1;" :: "r"(a), "r"(bytes) : "memory");
}
__device__ __forceinline__ void mbar_wait(uint32_t a, uint32_t parity) {
    asm volatile(
        "{\n\t.reg .pred P;\n\t"
        "WL%=:\n\t"
        "mbarrier.try_wait.parity.acquire.cta.shared::cta.b64 P, [%0], %1, 0x989680;\n\t"
        "@P bra WD%=;\n\t"
        "bra.uni WL%=;\n\t"
        "WD%=:\n\t}"
        :: "r"(a), "r"(parity) : "memory");
}
__device__ __forceinline__ void bulk_g2s(uint32_t dst_smem, const float* gsrc,
                                         uint32_t bytes, uint32_t mbar) {
    asm volatile(
        "cp.async.bulk.shared::cluster.global.mbarrier::complete_tx::bytes [%0], [%1], %2, [%3];"
        :: "r"(dst_smem), "l"(gsrc), "r"(bytes), "r"(mbar) : "memory");
}
#define FENCE_ASYNC() asm volatile("fence.proxy.async.shared::cta;" ::: "memory")

// SMEM (floats):
//   [0, 34816)        A_T[512][68]; reused after GEMM1: W4s[64][512]
//   [34816, 53248)    3 x 6144 GEMM1 weight stages; reused: act[64][192],
//                     then yS 2 x 8256
//   [53248, 57408)    sATT 16 x 260
//   [57408, 57416)    4 mbarriers
#define SMF 57416

__global__ void __launch_bounds__(768, 1)
fused_kernel(const float* __restrict__ x, float* __restrict__ out)
{
    extern __shared__ float sm[];
    float* sAT  = sm;                  // later: W4s
    float* sB   = sm + 34816;          // later: act, then yS buffers
    float* sATT = sm + 53248;
    const uint32_t smb  = smem_u32(sm);
    const uint32_t smbB = smb + 34816u * 4u;
    const uint32_t MBAR = smb + 57408u * 4u;   // +8*k, k=0..2 GEMM1, k=3 W4

    const int t    = threadIdx.x;
    const int warp = t >> 5;           // 24 warps
    const int lane = t & 31;
    const int rh   = warp & 1;
    const int cg1  = warp >> 1;        // GEMM1 col-group 0..11
    const int n0   = blockIdx.x * 16;

    if (t == 0) {
        mbar_init(MBAR + 0,  1);
        mbar_init(MBAR + 8,  1);
        mbar_init(MBAR + 16, 1);
        mbar_init(MBAR + 24, 1);
    }
    __syncthreads();
    if (t == 0) {
        #pragma unroll
        for (int b = 0; b < 3; b++) {
            mbar_expect_tx(MBAR + 8u * b, 24576);
            bulk_g2s(smbB + 24576u * b, g_W1t + b * 6144, 24576, MBAR + 8u * b);
        }
    }

    const float4* xb = (const float4*)x;

    // ---- Phase 0: gather xs into A_T[c][row], row=4*i+l (8-wf LDG pattern)
    {
        const int cl = lane >> 1;            // c within 16-block
        const int hs = lane & 1;             // h selector: 0 -> h=0, 1 -> h=2
        for (int u = warp; u < 512; u += 24) {
            int i  = u >> 5, cb = u & 31;
            int c  = cb * 16 + cl;
            long f4 = ((long)(n0 + i) * 512 + c) * 4 + hs * 2;
            float4 v = __ldg(&xb[f4]);
            *(float2*)&sAT[c * 68 + 4 * i + 2 * hs] = make_float2(v.x, v.z);
        }
    }
    __syncthreads();

    // ---- Phase 1: GEMM1 [64r][192c]; warp 32r x 16c; 3-deep TMA pipeline;
    //      explicit 1-iter software pipelining of LDS
    float2 acc[4][2];
    #pragma unroll
    for (int r = 0; r < 4; r++) {
        acc[r][0] = make_float2(0.f, 0.f);
        acc[r][1] = make_float2(0.f, 0.f);
    }
    const int r0 = rh * 32 + (lane >> 2) * 4;
    const int j0 = cg1 * 16 + (lane & 3) * 4;

    #define FMA8(av, bv)                                                        \
        do {                                                                    \
            float2 b01 = make_float2((bv).x, (bv).y);                           \
            float2 b23 = make_float2((bv).z, (bv).w);                           \
            acc[0][0] = ffma2(make_float2((av).x, (av).x), b01, acc[0][0]);     \
            acc[0][1] = ffma2(make_float2((av).x, (av).x), b23, acc[0][1]);     \
            acc[1][0] = ffma2(make_float2((av).y, (av).y), b01, acc[1][0]);     \
            acc[1][1] = ffma2(make_float2((av).y, (av).y), b23, acc[1][1]);     \
            acc[2][0] = ffma2(make_float2((av).z, (av).z), b01, acc[2][0]);     \
            acc[2][1] = ffma2(make_float2((av).z, (av).z), b23, acc[2][1]);     \
            acc[3][0] = ffma2(make_float2((av).w, (av).w), b01, acc[3][0]);     \
            acc[3][1] = ffma2(make_float2((av).w, (av).w), b23, acc[3][1]);     \
        } while (0)

    int buf = 0;
    for (int st = 0; st < 16; st++) {
        mbar_wait(MBAR + 8u * buf, ((unsigned)st / 3u) & 1u);

        const float* bbase = sB + buf * 6144 + j0;
        const float* abase = sAT + (st * 32) * 68 + r0;

        float4 a0 = *(const float4*)&abase[0];
        float4 b0 = *(const float4*)&bbase[0];
        #pragma unroll 31
        for (int kk = 0; kk < 31; kk++) {
            float4 a1 = *(const float4*)&abase[(kk + 1) * 68];
            float4 b1 = *(const float4*)&bbase[(kk + 1) * 192];
            FMA8(a0, b0);
            a0 = a1; b0 = b1;
        }
        FMA8(a0, b0);

        __syncthreads();   // buffer consumed by all warps

        if (st + 3 < 16 && t == 0) {
            mbar_expect_tx(MBAR + 8u * buf, 24576);
            bulk_g2s(smbB + 24576u * buf, g_W1t + (st + 3) * 6144, 24576,
                     MBAR + 8u * buf);
        }
        buf = (buf == 2) ? 0 : buf + 1;
    }
    // sAT & sB dead. Kick off full W4 load into old sAT region.
    if (t == 0) {
        FENCE_ASYNC();
        mbar_expect_tx(MBAR + 24, 131072);
        bulk_g2s(smb, g_W4t, 131072, MBAR + 24);
    }

    // ---- act = relu(acc + bias) -> act[64][192] in old sB region
    float* act = sB;
    {
        float4 bias = __ldg((const float4*)&g_b1f[j0]);
        #pragma unroll
        for (int r = 0; r < 4; r++) {
            float4 o;
            o.x = fmaxf(acc[r][0].x + bias.x, 0.f);
            o.y = fmaxf(acc[r][0].y + bias.y, 0.f);
            o.z = fmaxf(acc[r][1].x + bias.z, 0.f);
            o.w = fmaxf(acc[r][1].y + bias.w, 0.f);
            *(float4*)&act[(r0 + r) * 192 + j0] = o;
        }
    }
    __syncthreads();   // act complete

    // ---- Phase 2: warp-local 4x4 attention (warps 0..15, warp = sample)
    if (warp < 16) {
        const int s = warp, g = lane;
        float2 q2[4], k2[4], v2[4];
        #pragma unroll
        for (int l = 0; l < 4; l++) {
            const float* ar = act + (4 * s + l) * 192;
            q2[l] = *(const float2*)&ar[2 * g];
            k2[l] = *(const float2*)&ar[2 * g + 64];
            v2[l] = *(const float2*)&ar[2 * g + 128];
        }
        float sc[16];
        #pragma unroll
        for (int l = 0; l < 4; l++)
            #pragma unroll
            for (int m = 0; m < 4; m++)
                sc[l * 4 + m] = q2[l].x * k2[m].x + q2[l].y * k2[m].y;
        #pragma unroll
        for (int off = 16; off > 0; off >>= 1)
            #pragma unroll
            for (int i = 0; i < 16; i++)
                sc[i] += __shfl_xor_sync(0xffffffffu, sc[i], off);

        #pragma unroll
        for (int l = 0; l < 4; l++) {
            float s0 = sc[l*4+0], s1 = sc[l*4+1], s2 = sc[l*4+2], s3 = sc[l*4+3];
            float mx = fmaxf(fmaxf(s0, s1), fmaxf(s2, s3));
            float e0 = __expf(s0 - mx), e1 = __expf(s1 - mx);
            float e2 = __expf(s2 - mx), e3 = __expf(s3 - mx);
            float inv = 1.f / (e0 + e1 + e2 + e3);
            float ax = (e0*v2[0].x + e1*v2[1].x + e2*v2[2].x + e3*v2[3].x) * inv;
            float ay = (e0*v2[0].y + e1*v2[1].y + e2*v2[2].y + e3*v2[3].y) * inv;
            sATT[s * 260 + (2*g)   * 4 + l] = ax;
            sATT[s * 260 + (2*g+1) * 4 + l] = ay;
        }
    }
    __syncthreads();          // sATT complete; act dead -> yS region
    mbar_wait(MBAR + 24, 0);  // W4s resident

    // ---- Phase 3 (R8 alternation): GEMM2 warps<16; epilogue of prev chunk by
    //      warps 16..23; final epilogue by all 24.
    const float* W4s = sm;
    const int sI  = lane & 15;
    const int cgr = lane >> 4;

    auto compute_y = [&](int cc) {
        float* yb = sB + (cc & 1) * 8256;
        const int cb = cc * 128 + warp * 8 + cgr * 4;
        float2 y01[4], y23[4];
        #pragma unroll
        for (int cp = 0; cp < 4; cp++) {
            y01[cp] = make_float2(0.f, 0.f);
            y23[cp] = make_float2(0.f, 0.f);
        }
        const float* attn = sATT + sI * 260;
        const float* wp   = W4s + cb;
        float4 av = *(const float4*)&attn[0];
        float4 wv = *(const float4*)&wp[0];
        #pragma unroll 7
        for (int d = 0; d < 63; d++) {
            float4 avn = *(const float4*)&attn[(d + 1) * 4];
            float4 wvn = *(const float4*)&wp[(d + 1) * 512];
            float2 a01 = make_float2(av.x, av.y), a23 = make_float2(av.z, av.w);
            const float* wvp = &wv.x;
            #pragma unroll
            for (int cp = 0; cp < 4; cp++) {
                float2 wb = make_float2(wvp[cp], wvp[cp]);
                y01[cp] = ffma2(a01, wb, y01[cp]);
                y23[cp] = ffma2(a23, wb, y23[cp]);
            }
            av = avn; wv = wvn;
        }
        {
            float2 a01 = make_float2(av.x, av.y), a23 = make_float2(av.z, av.w);
            const float* wvp = &wv.x;
            #pragma unroll
            for (int cp = 0; cp < 4; cp++) {
                float2 wb = make_float2(wvp[cp], wvp[cp]);
                y01[cp] = ffma2(a01, wb, y01[cp]);
                y23[cp] = ffma2(a23, wb, y23[cp]);
            }
        }
        float4 cf = __ldg((const float4*)&g_c4f[cb]);
        const float* cfp = &cf.x;
        const int fb = (warp * 8 + cgr * 4) * 4;
        #pragma unroll
        for (int cp = 0; cp < 4; cp++) {
            *(float4*)&yb[sI * 516 + fb + cp * 4] =
                make_float4(y01[cp].x + cfp[cp], y01[cp].y + cfp[cp],
                            y23[cp].x + cfp[cp], y23[cp].y + cfp[cp]);
        }
    };
    auto epilogue = [&](int cc, int wfirst, int wcount) {
        const float* ys = sB + (cc & 1) * 8256;
        for (int u = warp - wfirst; u < 256; u += wcount) {
            const int s = u >> 4, i = u & 15;
            const int f = i * 32 + lane;
            float yv = ys[s * 516 + f];
            long b4i = ((long)(n0 + s) * 512 + cc * 128) * 4 + f;
            float4 v = __ldg(&xb[b4i]);
            v.x += yv; v.y += yv; v.z += yv; v.w += yv;
            ((float4*)out)[b4i] = v;
        }
    };

    if (warp < 16) compute_y(0);
    __syncthreads();
    #pragma unroll
    for (int cc = 1; cc < 4; cc++) {
        if (warp < 16) compute_y(cc);
        else           epilogue(cc - 1, 16, 8);
        __syncthreads();
    }
    epilogue(3, 0, 24);
}

extern "C" void kernel_launch(void* const* d_in, const int* in_sizes, int n_in,
                              void* d_out, int out_size)
{
    const float* x    = (const float*)d_in[0];
    const float* W123 = (const float*)d_in[1];
    const float* b123 = (const float*)d_in[2];
    const float* g123 = (const float*)d_in[3];
    const float* be123= (const float*)d_in[4];
    const float* m123 = (const float*)d_in[5];
    const float* v123 = (const float*)d_in[6];
    const float* W4   = (const float*)d_in[7];
    const float* b4   = (const float*)d_in[8];
    const float* g4   = (const float*)d_in[9];
    const float* be4  = (const float*)d_in[10];
    const float* m4   = (const float*)d_in[11];
    const float* v4   = (const float*)d_in[12];

    int N = in_sizes[0] / (512 * 16);   // 2048

    prep_kernel<<<515, 256>>>(W123, b123, g123, be123, m123, v123,
                              W4, b4, g4, be4, m4, v4);

    cudaFuncSetAttribute(fused_kernel, cudaFuncAttributeMaxDynamicSharedMemorySize,
                         SMF * 4);
    fused_kernel<<<N / 16, 768, SMF * 4>>>(x, (float*)d_out);
}